// round 15
// baseline (speedup 1.0000x reference)
#include <cuda_runtime.h>
#include <cuda_bf16.h>
#include <cstdint>

// Problem dims
#define NBAGS 512
#define MSENT 8
#define TLEN  64
#define IND   360
#define HD    230
#define G3    690
#define H2    460
#define OUTD  53
#define BALL  4096
#define ROWSALL 262144

// proj GEMM atoms (K 360->384, N 690->768)
#define KATOMS 24
#define MATOMS (ROWSALL/16)
#define NATOMS 96
// score GEMM atoms (K 460->480, N 460->512)
#define SK 30
// gru GEMM atoms (K 230->240, N 690->704)
#define GK 15
#define GN 88

// ---------------- scratch (static device globals) ----------------
__device__ float g_xg_f[(size_t)ROWSALL * G3];
__device__ float g_xg_r[(size_t)ROWSALL * G3];
__device__ float g_hcat[(size_t)ROWSALL * H2];
// proj fragments
__device__ __nv_bfloat16 g_Ahi[(size_t)MATOMS * KATOMS * 256];
__device__ __nv_bfloat16 g_Alo[(size_t)MATOMS * KATOMS * 256];
__device__ __nv_bfloat16 g_Bhi[(size_t)2 * NATOMS * KATOMS * 128];
__device__ __nv_bfloat16 g_Blo[(size_t)2 * NATOMS * KATOMS * 128];
// gru W fragments, interleaved per lane: {hi.x, hi.y, lo.x, lo.y}
__device__ uint4 g_Wg4[(size_t)2 * GN * GK * 32];
// word score X fragments (262144 rows)
__device__ __nv_bfloat16 g_Xwhi[(size_t)(ROWSALL/16) * SK * 256];
__device__ __nv_bfloat16 g_Xwlo[(size_t)(ROWSALL/16) * SK * 256];
// sentence score X fragments (4096 rows)
__device__ __nv_bfloat16 g_Xshi[(size_t)(BALL/16) * SK * 256];
__device__ __nv_bfloat16 g_Xslo[(size_t)(BALL/16) * SK * 256];
// score W fragments (word + sent)
__device__ __nv_bfloat16 g_Bw1hi[(size_t)64 * SK * 128];
__device__ __nv_bfloat16 g_Bw1lo[(size_t)64 * SK * 128];
__device__ __nv_bfloat16 g_Bw2hi[(size_t)64 * SK * 128];
__device__ __nv_bfloat16 g_Bw2lo[(size_t)64 * SK * 128];
__device__ float g_sw[ROWSALL];
__device__ float g_wv[(size_t)BALL * H2];
__device__ float g_ss[BALL];
__device__ float g_sv[(size_t)NBAGS * H2];

// ---------------- helpers ----------------
__device__ __forceinline__ unsigned pack_split(float x, float y, unsigned& lo)
{
    __nv_bfloat16 hx = __float2bfloat16(x);
    __nv_bfloat16 hy = __float2bfloat16(y);
    __nv_bfloat16 lx = __float2bfloat16(x - __bfloat162float(hx));
    __nv_bfloat16 ly = __float2bfloat16(y - __bfloat162float(hy));
    __nv_bfloat162 ph; ph.x = hx; ph.y = hy;
    __nv_bfloat162 pl; pl.x = lx; pl.y = ly;
    lo = *(unsigned*)&pl;
    return *(unsigned*)&ph;
}

__device__ __forceinline__ float tanh_fast(float x)
{
    float e = __expf(2.f * x);
    return 1.f - __fdividef(2.f, e + 1.f);
}

#define MMA16816(c, a, b) \
    asm volatile("mma.sync.aligned.m16n8k16.row.col.f32.bf16.bf16.f32 " \
        "{%0,%1,%2,%3}, {%4,%5,%6,%7}, {%8,%9}, {%0,%1,%2,%3};" \
        : "+f"((c)[0]), "+f"((c)[1]), "+f"((c)[2]), "+f"((c)[3]) \
        : "r"((a).x), "r"((a).y), "r"((a).z), "r"((a).w), "r"((b).x), "r"((b).y))

// =====================================================================
// pack A (bag) into mma fragment order, split bf16 hi/lo (proj, K=384)
// =====================================================================
__global__ void __launch_bounds__(256) k_pack_a(const float* __restrict__ bag)
{
    const int mi  = blockIdx.x;
    const int wid = threadIdx.x >> 5, lane = threadIdx.x & 31;
    const int gid = lane >> 2, tig = lane & 3;
    const size_t r0 = (size_t)mi * 16 + gid;
    const size_t r1 = r0 + 8;
    for (int ki = wid; ki < KATOMS; ki += 8) {
        const int kb = ki * 16 + tig * 2;
        float2 v0 = (kb     < IND) ? *(const float2*)(bag + r0 * IND + kb)     : make_float2(0.f, 0.f);
        float2 v1 = (kb     < IND) ? *(const float2*)(bag + r1 * IND + kb)     : make_float2(0.f, 0.f);
        float2 v2 = (kb + 8 < IND) ? *(const float2*)(bag + r0 * IND + kb + 8) : make_float2(0.f, 0.f);
        float2 v3 = (kb + 8 < IND) ? *(const float2*)(bag + r1 * IND + kb + 8) : make_float2(0.f, 0.f);
        uint4 hi, lo;
        hi.x = pack_split(v0.x, v0.y, lo.x);
        hi.y = pack_split(v1.x, v1.y, lo.y);
        hi.z = pack_split(v2.x, v2.y, lo.z);
        hi.w = pack_split(v3.x, v3.y, lo.w);
        size_t off = ((size_t)mi * KATOMS + ki) * 256 + lane * 8;
        *(uint4*)(g_Ahi + off) = hi;
        *(uint4*)(g_Alo + off) = lo;
    }
}

// =====================================================================
// pack W_ih (both dirs) into B fragment order (proj)
// =====================================================================
__global__ void __launch_bounds__(128) k_pack_b(const float* __restrict__ Wf, const float* __restrict__ Wr)
{
    const int b = blockIdx.x;
    const int dir = b / NATOMS, ni = b - dir * NATOMS;
    const float* W = dir ? Wr : Wf;
    const int wid = threadIdx.x >> 5, lane = threadIdx.x & 31;
    const int gid = lane >> 2, tig = lane & 3;
    const int n = ni * 8 + gid;
    const bool nok = (n < G3);
    for (int ki = wid; ki < KATOMS; ki += 4) {
        const int kb = ki * 16 + tig * 2;
        float2 v0 = (nok && kb     < IND) ? *(const float2*)(W + (size_t)n * IND + kb)     : make_float2(0.f, 0.f);
        float2 v1 = (nok && kb + 8 < IND) ? *(const float2*)(W + (size_t)n * IND + kb + 8) : make_float2(0.f, 0.f);
        uint2 hi, lo;
        hi.x = pack_split(v0.x, v0.y, lo.x);
        hi.y = pack_split(v1.x, v1.y, lo.y);
        size_t off = ((size_t)b * KATOMS + ki) * 128 + lane * 4;
        *(uint2*)(g_Bhi + off) = hi;
        *(uint2*)(g_Blo + off) = lo;
    }
}

// =====================================================================
// proj GEMM via mma.sync (verified)
// =====================================================================
__global__ void __launch_bounds__(256) k_mma_proj(const float* __restrict__ bf_, const float* __restrict__ br_)
{
    const int tid = threadIdx.x, wid = tid >> 5, lane = tid & 31;
    const int wm = wid >> 2, wn = wid & 3;
    const int m0 = blockIdx.y * 128;
    const int n0 = blockIdx.x * 128;
    const int dir = blockIdx.z;

    const __nv_bfloat16* Bh = g_Bhi + (size_t)dir * NATOMS * KATOMS * 128;
    const __nv_bfloat16* Bl = g_Blo + (size_t)dir * NATOMS * KATOMS * 128;

    const int miG0 = (m0 >> 4) + wm * 4;
    const int niG0 = (n0 >> 3) + wn * 4;

    float acc[4][4][4] = {};

    for (int ki = 0; ki < KATOMS; ki++) {
        uint4 ah[4], al[4];
        uint2 bh[4], bl[4];
        #pragma unroll
        for (int mi = 0; mi < 4; mi++) {
            size_t off = ((size_t)(miG0 + mi) * KATOMS + ki) * 256 + lane * 8;
            ah[mi] = *(const uint4*)(g_Ahi + off);
            al[mi] = *(const uint4*)(g_Alo + off);
        }
        #pragma unroll
        for (int ni = 0; ni < 4; ni++) {
            size_t off = ((size_t)(niG0 + ni) * KATOMS + ki) * 128 + lane * 4;
            bh[ni] = *(const uint2*)(Bh + off);
            bl[ni] = *(const uint2*)(Bl + off);
        }
        #pragma unroll
        for (int mi = 0; mi < 4; mi++)
            #pragma unroll
            for (int ni = 0; ni < 4; ni++) {
                MMA16816(acc[mi][ni], ah[mi], bh[ni]);
                MMA16816(acc[mi][ni], ah[mi], bl[ni]);
                MMA16816(acc[mi][ni], al[mi], bh[ni]);
            }
    }

    const float* bias = dir ? br_ : bf_;
    float* C = dir ? g_xg_r : g_xg_f;
    const int gid = lane >> 2, tig = lane & 3;
    #pragma unroll
    for (int mi = 0; mi < 4; mi++) {
        const size_t r0 = (size_t)m0 + wm * 64 + mi * 16 + gid;
        const size_t r1 = r0 + 8;
        #pragma unroll
        for (int ni = 0; ni < 4; ni++) {
            const int g = n0 + wn * 32 + ni * 8 + tig * 2;
            if (g < G3) {
                float2 bv = *(const float2*)(bias + g);
                float2 o0 = make_float2(acc[mi][ni][0] + bv.x, acc[mi][ni][1] + bv.y);
                float2 o1 = make_float2(acc[mi][ni][2] + bv.x, acc[mi][ni][3] + bv.y);
                *(float2*)(C + r0 * G3 + g) = o0;
                *(float2*)(C + r1 * G3 + g) = o1;
            }
        }
    }
}

// =====================================================================
// pack W_hh (both dirs) into interleaved B fragments (gru: N=704, K=240)
// uint4 per lane = {hi pair(k,k+1), hi pair(k+8,k+9), lo pair, lo pair}
// =====================================================================
__global__ void __launch_bounds__(128) k_pack_wgru(const float* __restrict__ Wf, const float* __restrict__ Wr)
{
    const int b = blockIdx.x;            // 0..2*GN-1
    const int dir = b / GN, na = b - dir * GN;
    const float* W = dir ? Wr : Wf;
    const int wid = threadIdx.x >> 5, lane = threadIdx.x & 31;
    const int gid = lane >> 2, tig = lane & 3;
    const int n = na * 8 + gid;
    for (int ki = wid; ki < GK; ki += 4) {
        const int kb = ki * 16 + tig * 2;
        float e0 = (n < G3 && kb     < HD) ? W[(size_t)n * HD + kb]     : 0.f;
        float e1 = (n < G3 && kb + 1 < HD) ? W[(size_t)n * HD + kb + 1] : 0.f;
        float e2 = (n < G3 && kb + 8 < HD) ? W[(size_t)n * HD + kb + 8] : 0.f;
        float e3 = (n < G3 && kb + 9 < HD) ? W[(size_t)n * HD + kb + 9] : 0.f;
        uint4 v;
        v.x = pack_split(e0, e1, v.z);
        v.y = pack_split(e2, e3, v.w);
        g_Wg4[((size_t)b * GK + ki) * 32 + lane] = v;
    }
}

// =====================================================================
// GRU via mma.sync, v2: 64 rows/CTA, 128 CTAs (single wave).
// Per step, two 32-row halves: in-register A-frag build from h_s,
// 8 warps x 11 n-atoms x 15 k-atoms x 2 m-atoms x 3 split MMAs -> hg -> gates.
// smem: h_s 64x240 f32 | hg 32x690 f32 | bias 690  = 152,520 B
// =====================================================================
__global__ void __launch_bounds__(256) k_gru_mma(const float* __restrict__ bhhf,
                                                 const float* __restrict__ bhhr)
{
    extern __shared__ float sm[];
    float* h_s = sm;                 // 64*240
    float* hg  = sm + 64 * 240;      // 32*690
    float* bb  = hg + 32 * G3;       // 690

    const int bx  = blockIdx.x;      // 0..127
    const int dir = bx >> 6;
    const int rb  = (bx & 63) * 64;
    const float* bhh = dir ? bhhr : bhhf;
    const float* xg  = dir ? g_xg_r : g_xg_f;
    const uint4* WF = g_Wg4 + (size_t)dir * GN * GK * 32;

    const int tid = threadIdx.x, wid = tid >> 5, lane = tid & 31;
    const int gid = lane >> 2, tig = lane & 3;

    for (int i = tid; i < 64 * 240; i += 256) h_s[i] = 0.f;
    for (int i = tid; i < G3; i += 256) bb[i] = bhh[i];
    __syncthreads();

    for (int ti = 0; ti < TLEN; ti++) {
        const int t = dir ? (TLEN - 1 - ti) : ti;

        #pragma unroll 1
        for (int half = 0; half < 2; half++) {
            float acc[2][11][4];
            #pragma unroll
            for (int mi = 0; mi < 2; mi++)
                #pragma unroll
                for (int ni = 0; ni < 11; ni++)
                    #pragma unroll
                    for (int r = 0; r < 4; r++) acc[mi][ni][r] = 0.f;

            #pragma unroll 1
            for (int ki = 0; ki < GK; ki++) {
                // build A fragments in registers straight from h_s
                uint4 ah[2], al[2];
                const int k0 = ki * 16 + tig * 2;
                #pragma unroll
                for (int mi = 0; mi < 2; mi++) {
                    const int row = half * 32 + mi * 16 + gid;
                    float2 p0 = *(const float2*)(h_s + row * 240 + k0);
                    float2 p1 = *(const float2*)(h_s + (row + 8) * 240 + k0);
                    float2 p2 = *(const float2*)(h_s + row * 240 + k0 + 8);
                    float2 p3 = *(const float2*)(h_s + (row + 8) * 240 + k0 + 8);
                    ah[mi].x = pack_split(p0.x, p0.y, al[mi].x);
                    ah[mi].y = pack_split(p1.x, p1.y, al[mi].y);
                    ah[mi].z = pack_split(p2.x, p2.y, al[mi].z);
                    ah[mi].w = pack_split(p3.x, p3.y, al[mi].w);
                }
                #pragma unroll
                for (int ni = 0; ni < 11; ni++) {
                    uint4 w = WF[((size_t)(wid * 11 + ni) * GK + ki) * 32 + lane];
                    uint2 bh; bh.x = w.x; bh.y = w.y;
                    uint2 bl; bl.x = w.z; bl.y = w.w;
                    MMA16816(acc[0][ni], ah[0], bh);
                    MMA16816(acc[0][ni], ah[0], bl);
                    MMA16816(acc[0][ni], al[0], bh);
                    MMA16816(acc[1][ni], ah[1], bh);
                    MMA16816(acc[1][ni], ah[1], bl);
                    MMA16816(acc[1][ni], al[1], bh);
                }
            }

            // store hg (+bias) for this 32-row half (local rows 0..31)
            #pragma unroll
            for (int mi = 0; mi < 2; mi++) {
                int r0 = mi * 16 + gid, r1 = r0 + 8;
                #pragma unroll
                for (int ni = 0; ni < 11; ni++) {
                    int n = wid * 88 + ni * 8 + tig * 2;
                    if (n < G3) {
                        float b0 = bb[n], b1 = bb[n + 1];
                        hg[r0 * G3 + n]     = acc[mi][ni][0] + b0;
                        hg[r0 * G3 + n + 1] = acc[mi][ni][1] + b1;
                        hg[r1 * G3 + n]     = acc[mi][ni][2] + b0;
                        hg[r1 * G3 + n + 1] = acc[mi][ni][3] + b1;
                    }
                }
            }
            __syncthreads();   // hg complete; all h_s reads for this half done

            // gates + state update + output for rows half*32 .. half*32+31
            for (int e = tid; e < 32 * HD; e += 256) {
                int rloc = e / HD, j = e - rloc * HD;
                int row = half * 32 + rloc;
                size_t xb = ((size_t)(rb + row) * TLEN + t) * G3;
                float xr = xg[xb + j];
                float xz = xg[xb + HD + j];
                float xn = xg[xb + 2 * HD + j];
                float hgr = hg[rloc * G3 + j];
                float hgz = hg[rloc * G3 + HD + j];
                float hgn = hg[rloc * G3 + 2 * HD + j];
                float rr = __fdividef(1.f, 1.f + __expf(-(xr + hgr)));
                float zz = __fdividef(1.f, 1.f + __expf(-(xz + hgz)));
                float nn = tanh_fast(xn + rr * hgn);
                float hold = h_s[row * 240 + j];
                float hn = (1.f - zz) * nn + zz * hold;
                h_s[row * 240 + j] = hn;
                g_hcat[((size_t)(rb + row) * TLEN + t) * H2 + dir * HD + j] = hn;
            }
            __syncthreads();   // gates done; hg free for next half / h_s stable
        }
    }
}

// =====================================================================
// pack X rows [R x 460] into A fragment order (score, K=480)
// =====================================================================
__global__ void __launch_bounds__(256) k_pack_x(const float* __restrict__ X,
        __nv_bfloat16* __restrict__ hi_, __nv_bfloat16* __restrict__ lo_)
{
    const int mi  = blockIdx.x;
    const int wid = threadIdx.x >> 5, lane = threadIdx.x & 31;
    const int gid = lane >> 2, tig = lane & 3;
    const size_t r0 = (size_t)mi * 16 + gid;
    const size_t r1 = r0 + 8;
    for (int ki = wid; ki < SK; ki += 8) {
        const int kb = ki * 16 + tig * 2;
        float2 z = make_float2(0.f, 0.f);
        float2 v0 = (kb     < H2) ? *(const float2*)(X + r0 * H2 + kb)     : z;
        float2 v1 = (kb     < H2) ? *(const float2*)(X + r1 * H2 + kb)     : z;
        float2 v2 = (kb + 8 < H2) ? *(const float2*)(X + r0 * H2 + kb + 8) : z;
        float2 v3 = (kb + 8 < H2) ? *(const float2*)(X + r1 * H2 + kb + 8) : z;
        uint4 hi, lo;
        hi.x = pack_split(v0.x, v0.y, lo.x);
        hi.y = pack_split(v1.x, v1.y, lo.y);
        hi.z = pack_split(v2.x, v2.y, lo.z);
        hi.w = pack_split(v3.x, v3.y, lo.w);
        size_t off = ((size_t)mi * SK + ki) * 256 + lane * 8;
        *(uint4*)(hi_ + off) = hi;
        *(uint4*)(lo_ + off) = lo;
    }
}

// =====================================================================
// pack score W [460 x 460] into B fragment order; source W[k][n]
// =====================================================================
__global__ void __launch_bounds__(128) k_pack_wsc(const float* __restrict__ W,
        __nv_bfloat16* __restrict__ hi_, __nv_bfloat16* __restrict__ lo_)
{
    const int na  = blockIdx.x;          // 0..63
    const int wid = threadIdx.x >> 5, lane = threadIdx.x & 31;
    const int gid = lane >> 2, tig = lane & 3;
    const int n = na * 8 + gid;
    for (int ki = wid; ki < SK; ki += 4) {
        const int kb = ki * 16 + tig * 2;
        float e0 = (n < H2 && kb     < H2) ? W[(size_t)(kb)     * H2 + n] : 0.f;
        float e1 = (n < H2 && kb + 1 < H2) ? W[(size_t)(kb + 1) * H2 + n] : 0.f;
        float e2 = (n < H2 && kb + 8 < H2) ? W[(size_t)(kb + 8) * H2 + n] : 0.f;
        float e3 = (n < H2 && kb + 9 < H2) ? W[(size_t)(kb + 9) * H2 + n] : 0.f;
        uint2 hi, lo;
        hi.x = pack_split(e0, e1, lo.x);
        hi.y = pack_split(e2, e3, lo.y);
        size_t off = ((size_t)na * SK + ki) * 128 + lane * 4;
        *(uint2*)(hi_ + off) = hi;
        *(uint2*)(lo_ + off) = lo;
    }
}

// =====================================================================
// score via mma.sync: s[row] = sum_n p[n]*tanh( (X@W)[row][n] + b[n] )
// CTA = 128 rows; N=512 in 4 passes of 128; K=480. Fused tanh+dot epilogue.
// =====================================================================
__global__ void __launch_bounds__(256) k_score_mma(
        const __nv_bfloat16* __restrict__ Xhi, const __nv_bfloat16* __restrict__ Xlo,
        const __nv_bfloat16* __restrict__ Bh_, const __nv_bfloat16* __restrict__ Bl_,
        const float* __restrict__ b, const float* __restrict__ p,
        float* __restrict__ sout)
{
    __shared__ float p_s[H2], b_s[H2];
    __shared__ float red[4][128];
    const int tid = threadIdx.x, wid = tid >> 5, lane = tid & 31;
    const int wm = wid >> 2, wn = wid & 3;
    const int gid = lane >> 2, tig = lane & 3;
    const int r0 = blockIdx.x * 128;
    for (int i = tid; i < H2; i += 256) { p_s[i] = p[i]; b_s[i] = b[i]; }
    __syncthreads();

    float rs[4][2] = {};
    const int ma0 = blockIdx.x * 8 + wm * 4;

    for (int pass = 0; pass < 4; pass++) {
        float acc[4][4][4] = {};
        for (int ki = 0; ki < SK; ki++) {
            uint4 ah[4], al[4];
            #pragma unroll
            for (int mi = 0; mi < 4; mi++) {
                size_t off = ((size_t)(ma0 + mi) * SK + ki) * 256 + lane * 8;
                ah[mi] = *(const uint4*)(Xhi + off);
                al[mi] = *(const uint4*)(Xlo + off);
            }
            uint2 bh[4], bl[4];
            #pragma unroll
            for (int ni = 0; ni < 4; ni++) {
                size_t off = ((size_t)(pass * 16 + wn * 4 + ni) * SK + ki) * 128 + lane * 4;
                bh[ni] = *(const uint2*)(Bh_ + off);
                bl[ni] = *(const uint2*)(Bl_ + off);
            }
            #pragma unroll
            for (int mi = 0; mi < 4; mi++)
                #pragma unroll
                for (int ni = 0; ni < 4; ni++) {
                    MMA16816(acc[mi][ni], ah[mi], bh[ni]);
                    MMA16816(acc[mi][ni], ah[mi], bl[ni]);
                    MMA16816(acc[mi][ni], al[mi], bh[ni]);
                }
        }
        #pragma unroll
        for (int mi = 0; mi < 4; mi++)
            #pragma unroll
            for (int ni = 0; ni < 4; ni++) {
                int n = pass * 128 + wn * 32 + ni * 8 + tig * 2;
                if (n < H2) {
                    float p0 = p_s[n], p1 = p_s[n + 1];
                    float b0 = b_s[n], b1 = b_s[n + 1];
                    rs[mi][0] += p0 * tanh_fast(acc[mi][ni][0] + b0)
                               + p1 * tanh_fast(acc[mi][ni][1] + b1);
                    rs[mi][1] += p0 * tanh_fast(acc[mi][ni][2] + b0)
                               + p1 * tanh_fast(acc[mi][ni][3] + b1);
                }
            }
    }

    #pragma unroll
    for (int mi = 0; mi < 4; mi++)
        #pragma unroll
        for (int h = 0; h < 2; h++) {
            float v = rs[mi][h];
            v += __shfl_xor_sync(0xffffffffu, v, 1);
            v += __shfl_xor_sync(0xffffffffu, v, 2);
            rs[mi][h] = v;
        }
    if (tig == 0) {
        #pragma unroll
        for (int mi = 0; mi < 4; mi++) {
            red[wn][wm * 64 + mi * 16 + gid]     = rs[mi][0];
            red[wn][wm * 64 + mi * 16 + gid + 8] = rs[mi][1];
        }
    }
    __syncthreads();
    if (tid < 128)
        sout[r0 + tid] = red[0][tid] + red[1][tid] + red[2][tid] + red[3][tid];
}

// =====================================================================
// K4: softmax + weighted sum
// =====================================================================
__global__ void k_attnsum(const float* __restrict__ s, const float* __restrict__ X,
                          float* __restrict__ V, int L)
{
    __shared__ float sv[64];
    __shared__ float alpha[64];
    const int b = blockIdx.x;
    const int tid = threadIdx.x;
    if (tid < L) sv[tid] = s[b * L + tid];
    __syncthreads();
    float m = -1e30f;
    for (int l = 0; l < L; l++) m = fmaxf(m, sv[l]);
    float den = 0.f;
    for (int l = 0; l < L; l++) den += __expf(sv[l] - m);
    if (tid < L) alpha[tid] = __expf(sv[tid] - m) / den;
    __syncthreads();
    for (int j = tid; j < H2; j += blockDim.x) {
        float acc = 0.f;
        for (int l = 0; l < L; l++)
            acc += alpha[l] * X[((size_t)b * L + l) * H2 + j];
        V[(size_t)b * H2 + j] = acc;
    }
}

// =====================================================================
// K5: FC + scatter
// =====================================================================
__global__ void k_fc_scatter(const float* __restrict__ fcW, const float* __restrict__ fcb,
                             const int* __restrict__ pairs, float* __restrict__ out)
{
    __shared__ float sv[H2];
    const int r = blockIdx.x;
    const int tid = threadIdx.x;
    for (int j = tid; j < H2; j += blockDim.x) sv[j] = g_sv[(size_t)r * H2 + j];
    __syncthreads();
    if (tid < OUTD) {
        float acc = fcb[tid];
        for (int j = 0; j < H2; j++) acc += sv[j] * fcW[(size_t)tid * H2 + j];
        int p0 = pairs[r * 3], p1 = pairs[r * 3 + 1], p2 = pairs[r * 3 + 2];
        out[((size_t)(p0 * 64 + p1 * 8 + p2)) * OUTD + tid] = acc;
    }
}

__global__ void k_zero(float* __restrict__ out, int n)
{
    int i = blockIdx.x * blockDim.x + threadIdx.x;
    if (i < n) out[i] = 0.f;
}

// =====================================================================
extern "C" void kernel_launch(void* const* d_in, const int* in_sizes, int n_in,
                              void* d_out, int out_size)
{
    const float* bag   = (const float*)d_in[0];
    const float* Wihf  = (const float*)d_in[1];
    const float* Whhf  = (const float*)d_in[2];
    const float* bihf  = (const float*)d_in[3];
    const float* bhhf  = (const float*)d_in[4];
    const float* Wihr  = (const float*)d_in[5];
    const float* Whhr  = (const float*)d_in[6];
    const float* bihr  = (const float*)d_in[7];
    const float* bhhr  = (const float*)d_in[8];
    const float* Wword = (const float*)d_in[9];
    const float* bword = (const float*)d_in[10];
    const float* pword = (const float*)d_in[11];
    const float* Wsent = (const float*)d_in[12];
    const float* bsent = (const float*)d_in[13];
    const float* psent = (const float*)d_in[14];
    const float* fcW   = (const float*)d_in[15];
    const float* fcb   = (const float*)d_in[16];
    const int*   pairs = (const int*)d_in[17];
    float* out = (float*)d_out;

    void *p_hcat, *p_sw, *p_wv, *p_ss, *p_sv;
    void *p_xwhi, *p_xwlo, *p_xshi, *p_xslo;
    void *p_bw1hi, *p_bw1lo, *p_bw2hi, *p_bw2lo;
    cudaGetSymbolAddress(&p_hcat,  g_hcat);
    cudaGetSymbolAddress(&p_sw,    g_sw);
    cudaGetSymbolAddress(&p_wv,    g_wv);
    cudaGetSymbolAddress(&p_ss,    g_ss);
    cudaGetSymbolAddress(&p_sv,    g_sv);
    cudaGetSymbolAddress(&p_xwhi,  g_Xwhi);
    cudaGetSymbolAddress(&p_xwlo,  g_Xwlo);
    cudaGetSymbolAddress(&p_xshi,  g_Xshi);
    cudaGetSymbolAddress(&p_xslo,  g_Xslo);
    cudaGetSymbolAddress(&p_bw1hi, g_Bw1hi);
    cudaGetSymbolAddress(&p_bw1lo, g_Bw1lo);
    cudaGetSymbolAddress(&p_bw2hi, g_Bw2hi);
    cudaGetSymbolAddress(&p_bw2lo, g_Bw2lo);

    // gru smem: h_s 64x240 + hg 32x690 + bias 690 (floats)
    const size_t smem_gru = (size_t)(64 * 240 + 32 * G3 + G3) * 4; // 152,520 B
    cudaFuncSetAttribute(k_gru_mma, cudaFuncAttributeMaxDynamicSharedMemorySize, (int)smem_gru);

    // 1) zero output (poisoned by harness)
    k_zero<<<(out_size + 255) / 256, 256>>>(out, out_size);

    // 2) proj: pack + HMMA GEMM
    k_pack_a<<<MATOMS, 256>>>(bag);
    k_pack_b<<<2 * NATOMS, 128>>>(Wihf, Wihr);
    dim3 gmma(6, ROWSALL / 128, 2);
    k_mma_proj<<<gmma, 256>>>(bihf, bihr);

    // 3) GRU: pack interleaved W_hh fragments + single-wave recurrent mma kernel
    k_pack_wgru<<<2 * GN, 128>>>(Whhf, Whhr);
    k_gru_mma<<<128, 256, smem_gru>>>(bhhf, bhhr);

    // 4) word attention
    k_pack_x<<<ROWSALL / 16, 256>>>((const float*)p_hcat, (__nv_bfloat16*)p_xwhi, (__nv_bfloat16*)p_xwlo);
    k_pack_wsc<<<64, 128>>>(Wword, (__nv_bfloat16*)p_bw1hi, (__nv_bfloat16*)p_bw1lo);
    k_score_mma<<<ROWSALL / 128, 256>>>(
        (const __nv_bfloat16*)p_xwhi, (const __nv_bfloat16*)p_xwlo,
        (const __nv_bfloat16*)p_bw1hi, (const __nv_bfloat16*)p_bw1lo,
        bword, pword, (float*)p_sw);
    k_attnsum<<<BALL, 256>>>((const float*)p_sw, (const float*)p_hcat, (float*)p_wv, TLEN);

    // 5) sentence attention
    k_pack_x<<<BALL / 16, 256>>>((const float*)p_wv, (__nv_bfloat16*)p_xshi, (__nv_bfloat16*)p_xslo);
    k_pack_wsc<<<64, 128>>>(Wsent, (__nv_bfloat16*)p_bw2hi, (__nv_bfloat16*)p_bw2lo);
    k_score_mma<<<BALL / 128, 256>>>(
        (const __nv_bfloat16*)p_xshi, (const __nv_bfloat16*)p_xslo,
        (const __nv_bfloat16*)p_bw2hi, (const __nv_bfloat16*)p_bw2lo,
        bsent, psent, (float*)p_ss);
    k_attnsum<<<NBAGS, 256>>>((const float*)p_ss, (const float*)p_wv, (float*)p_sv, MSENT);

    // 6) FC + scatter
    k_fc_scatter<<<NBAGS, 64>>>(fcW, fcb, pairs, out);
}